// round 4
// baseline (speedup 1.0000x reference)
#include <cuda_runtime.h>
#include <cstdint>
#include <cfloat>

// SQuant 4-bit adaptive rounding, fused single kernel (round 4).
// 256 threads/block, 4 kernel-groups/thread, 4 blocks/SM.
// No int8 staging: dequantized output built in-place in s_w (pass-2 flip
// targets are always thread-local), epilogue is a coalesced float4 copy.
// Pass-2 k-th largest via 3-probe quadsection (1 barrier per 4x shrink).

#define NROWS   1024
#define ROWLEN  9216
#define NV4     2304
#define NT      256
#define NGROUP  4
#define NWARP   8

// shared layout (dynamic):
//   [0,     36864) s_w   : row floats (input, overwritten with output)
//   [36864, 36928) s_red : 16 floats (per-warp max[8], min[8])
//   [36928, 36960) s_sum : 8 floats  (per-warp residual-error sums)
//   [36960, 37088) s_cnt : 2 parities x (8 + 8) ints
#define OFF_RED 36864
#define OFF_SUM 36928
#define OFF_CNT 36960
#define SMEM_BYTES 37088

__device__ __forceinline__ float warpSum(float v) {
#pragma unroll
    for (int o = 16; o; o >>= 1) v += __shfl_xor_sync(0xffffffffu, v, o);
    return v;
}
__device__ __forceinline__ float warpMaxR(float v) {
#pragma unroll
    for (int o = 16; o; o >>= 1) v = fmaxf(v, __shfl_xor_sync(0xffffffffu, v, o));
    return v;
}
__device__ __forceinline__ float warpMinR(float v) {
#pragma unroll
    for (int o = 16; o; o >>= 1) v = fminf(v, __shfl_xor_sync(0xffffffffu, v, o));
    return v;
}

// two block-wide sums in ONE barrier (parity double-buffered scratch)
__device__ __forceinline__ void blockCount2(int a, int b, int* s_cnt, int parity,
                                            int wid, int lane, int& A, int& B) {
    int aw = __reduce_add_sync(0xffffffffu, a);
    int bw = __reduce_add_sync(0xffffffffu, b);
    int* p = s_cnt + parity * 16;
    if (lane == 0) { p[wid] = aw; p[NWARP + wid] = bw; }
    __syncthreads();
    int A_ = 0, B_ = 0;
#pragma unroll
    for (int i = 0; i < NWARP; i++) { A_ += p[i]; B_ += p[NWARP + i]; }
    A = A_; B = B_;
}

__global__ void __launch_bounds__(NT, 4)
squant_kernel(const float* __restrict__ w, float* __restrict__ out)
{
    extern __shared__ unsigned char smem[];
    float* s_w   = (float*)smem;
    float* s_red = (float*)(smem + OFF_RED);
    float* s_sum = (float*)(smem + OFF_SUM);
    int*   s_cnt = (int*)(smem + OFF_CNT);

    const int tid  = threadIdx.x;
    const int lane = tid & 31;
    const int wid  = tid >> 5;

    const float4* __restrict__ w4 = (const float4*)(w + (size_t)blockIdx.x * ROWLEN);
    float4* sw4 = (float4*)s_w;

    // ---- vectorized load + min/max (1 barrier) ----
    float vmax = -FLT_MAX, vmin = FLT_MAX;
#pragma unroll
    for (int i = tid; i < NV4; i += NT) {
        float4 v = w4[i];
        sw4[i] = v;
        vmax = fmaxf(vmax, fmaxf(fmaxf(v.x, v.y), fmaxf(v.z, v.w)));
        vmin = fminf(vmin, fminf(fminf(v.x, v.y), fminf(v.z, v.w)));
    }
    vmax = warpMaxR(vmax);
    vmin = warpMinR(vmin);
    if (lane == 0) { s_red[wid] = vmax; s_red[NWARP + wid] = vmin; }
    __syncthreads();                       // also publishes s_w
    float m = s_red[0], n = s_red[NWARP];
#pragma unroll
    for (int i = 1; i < NWARP; i++) {
        m = fmaxf(m, s_red[i]);
        n = fminf(n, s_red[NWARP + i]);
    }
    const float scale = 15.0f / fmaxf(m - n, 1e-8f);
    const float zp    = rintf(scale * n) + 8.0f;
    const float inv   = 1.0f / scale;
    const float zpinv = zp * inv;

    // ---- pass 1: SQuant-K, 4 groups/thread; dequant written in-place ----
    float    Pup[NGROUP], Pdn[NGROUP];
    unsigned IVup[NGROUP], IVdn[NGROUP];   // (elem_idx << 8) | (val + 32)
    float er_tot = 0.f;

#pragma unroll
    for (int g = 0; g < NGROUP; g++) {
        const int base = (g * NT + tid) * 9;
        float rv[9], ev[9];
        unsigned cu = 0, cd = 0;
        float e = 0.f;
#pragma unroll
        for (int j = 0; j < 9; j++) {
            float qq = fmaf(scale, s_w[base + j], -zp);
            float rr = rintf(qq);
            float ee = rr - qq;
            rv[j] = rr; ev[j] = ee;
            if (ee < 0.f && qq <  7.f) cu |= (1u << j);
            if (ee > 0.f && qq > -8.f) cd |= (1u << j);
            e += ee;
        }
        const bool is_up = (e < 0.f);
        int nflip = (int)rintf(fabsf(e));   // mathematically <= 5
        if (nflip > 8) nflip = 8;
        const unsigned cand = is_up ? cu : cd;

        unsigned pu[9];
#pragma unroll
        for (int j = 0; j < 9; j++)
            pu[j] = ((cand >> j) & 1u) ? (__float_as_uint(ev[j]) & 0x7fffffffu) : 0u;

        // stable descending ranks via shared pairwise compares (36 compares)
        int rk[9];
#pragma unroll
        for (int j = 0; j < 9; j++) rk[j] = 0;
#pragma unroll
        for (int j = 1; j < 9; j++)
#pragma unroll
            for (int i = 0; i < j; i++) {
                bool c = pu[i] >= pu[j];
                rk[j] += c ? 1 : 0;
                rk[i] += c ? 0 : 1;
            }

        const float dir = is_up ? 1.f : -1.f;
        float er = 0.f;
        unsigned uN = 0, uL = 0;
        float vN = 0.f, vL = 0.f;
        int iN = 0, iL = 0;
#pragma unroll
        for (int j = 0; j < 9; j++) {
            bool c = (cand >> j) & 1u;
            float vflip = c ? rv[j] + dir : rv[j];     // value if flipped
            float nef   = c ? ev[j] + dir : 0.f;       // err if flipped
            bool f = rk[j] < nflip;
            float nr = f ? vflip : rv[j];
            float ne = f ? nef : ev[j];
            er += ne;
            float oc = fminf(7.f, fmaxf(-8.f, nr));    // clip + dequant in regs
            s_w[base + j] = fmaf(oc, inv, zpinv);
            if (rk[j] == nflip)     { uN = pu[j]; vN = vflip; iN = j; }
            if (rk[j] == nflip - 1) { uL = pu[j]; vL = rv[j]; iL = j; }
        }
        er_tot += er;

        const bool hasL = (nflip > 0);
        const float priN = __uint_as_float(uN);                 // candN ? |errN| : 0
        const float priL = hasL ? (1.f - __uint_as_float(uL)) : 0.f;
        const float valL = hasL ? vL : vN;
        const int   idxN = base + iN;
        const int   idxL = hasL ? base + iL : idxN;
        const unsigned ivN = ((unsigned)idxN << 8) | (unsigned)(__float2int_rn(vN) + 32);
        const unsigned ivL = ((unsigned)idxL << 8) | (unsigned)(__float2int_rn(valL) + 32);

        if (is_up) { Pup[g] = priN; IVup[g] = ivN; Pdn[g] = priL; IVdn[g] = ivL; }
        else       { Pdn[g] = priN; IVdn[g] = ivN; Pup[g] = priL; IVup[g] = ivL; }
    }

    // ---- row residual-error reduction (1 barrier) ----
    {
        float s = warpSum(er_tot);
        if (lane == 0) s_sum[wid] = s;
    }
    __syncthreads();
    float e2 = s_sum[0];
#pragma unroll
    for (int i = 1; i < NWARP; i++) e2 += s_sum[i];

    const bool up2 = (e2 < 0.f);
    int k = (int)rintf(fabsf(e2));
    if (k > NT * NGROUP) k = NT * NGROUP;

    unsigned U[NGROUP], IV[NGROUP];
#pragma unroll
    for (int g = 0; g < NGROUP; g++) {
        U[g]  = __float_as_uint(up2 ? Pup[g] : Pdn[g]);   // P >= 0 -> bits monotone
        IV[g] = up2 ? IVup[g] : IVdn[g];
    }

    // ---- pass-2 selection: 3-probe quadsection for k-th largest ----
    if (k > 0) {
        int parity = 0;
        unsigned lo = 0u, hi = 0x3F800000u;  // cnt(>=lo)>=k, cnt(>=hi+1)<k
        bool found = false;
        unsigned thr = 0;
        while (lo < hi) {
            float lof = __uint_as_float(lo), hif = __uint_as_float(hi);
            float d = hif - lof;
            unsigned t1 = __float_as_uint(fmaf(0.25f, d, lof));
            unsigned t2 = __float_as_uint(fmaf(0.50f, d, lof));
            unsigned t3 = __float_as_uint(fmaf(0.75f, d, lof));
            t1 = t1 < lo + 1 ? lo + 1 : (t1 > hi ? hi : t1);
            t2 = t2 < t1 ? t1 : (t2 > hi ? hi : t2);
            t3 = t3 < t2 ? t2 : (t3 > hi ? hi : t3);
            int a = 0, b = 0;
#pragma unroll
            for (int g = 0; g < NGROUP; g++) {
                a += (U[g] >= t1) ? 1 : 0;
                a += (U[g] >= t2) ? 0x10000 : 0;
                b += (U[g] >= t3) ? 1 : 0;
            }
            int A, B; blockCount2(a, b, s_cnt, parity, wid, lane, A, B); parity ^= 1;
            int c1 = A & 0xFFFF, c2 = A >> 16, c3 = B;
            if (c1 == k) { thr = t1; found = true; break; }
            if (c2 == k) { thr = t2; found = true; break; }
            if (c3 == k) { thr = t3; found = true; break; }
            if      (c3 > k) { lo = t3; }
            else if (c2 > k) { lo = t2; hi = t3 - 1; }
            else if (c1 > k) { lo = t1; hi = t2 - 1; }
            else             { hi = t1 - 1; }
        }
        if (found) {
#pragma unroll
            for (int g = 0; g < NGROUP; g++)
                if (U[g] >= thr) {
                    int idx = (int)(IV[g] >> 8);
                    float vf = (float)((int)(IV[g] & 0xFFu) - 32);
                    s_w[idx] = fmaf(fminf(7.f, fmaxf(-8.f, vf)), inv, zpinv);
                }
        } else {
            // exact ties at the k-th priority: resolve by ascending element index
            const unsigned Uk = lo;
            int clg = 0;
#pragma unroll
            for (int g = 0; g < NGROUP; g++) clg += (U[g] > Uk) ? 1 : 0;
            int cGT, dummy;
            blockCount2(clg, 0, s_cnt, parity, wid, lane, cGT, dummy); parity ^= 1;
            int rem = k - cGT;                  // >= 1
            int ilo = 0, ihi = ROWLEN, mI = ROWLEN;
            for (;;) {
                mI = (ilo + ihi + 1) >> 1;
                int ct = 0;
#pragma unroll
                for (int g = 0; g < NGROUP; g++)
                    ct += ((U[g] == Uk) && (int)(IV[g] >> 8) < mI) ? 1 : 0;
                int c;
                blockCount2(ct, 0, s_cnt, parity, wid, lane, c, dummy); parity ^= 1;
                if (c == rem) break;            // unique indices -> always reachable
                if (c < rem) ilo = mI; else ihi = mI - 1;
            }
#pragma unroll
            for (int g = 0; g < NGROUP; g++)
                if (U[g] > Uk || (U[g] == Uk && (int)(IV[g] >> 8) < mI)) {
                    int idx = (int)(IV[g] >> 8);
                    float vf = (float)((int)(IV[g] & 0xFFu) - 32);
                    s_w[idx] = fmaf(fminf(7.f, fmaxf(-8.f, vf)), inv, zpinv);
                }
        }
    }
    __syncthreads();

    // ---- coalesced copy out ----
    float4* __restrict__ orow4 = (float4*)(out + (size_t)blockIdx.x * ROWLEN);
    const float4* swc = (const float4*)s_w;
#pragma unroll
    for (int i = tid; i < NV4; i += NT)
        orow4[i] = swc[i];
}

extern "C" void kernel_launch(void* const* d_in, const int* in_sizes, int n_in,
                              void* d_out, int out_size)
{
    const float* w = (const float*)d_in[0];
    float* out = (float*)d_out;
    squant_kernel<<<NROWS, NT, SMEM_BYTES>>>(w, out);
}

// round 5
// speedup vs baseline: 1.1914x; 1.1914x over previous
#include <cuda_runtime.h>
#include <cstdint>
#include <cfloat>

// SQuant 4-bit adaptive rounding (round 5 = round 3 + float-pipe selection).
// 256 threads/block, 4 kernel-groups/thread, 4 blocks/SM.
// Pass-1 rank/flip math in float domain (FADD/FSEL on fma pipe) to balance
// the overloaded alu pipe. Structure otherwise identical to round 3 (34.8us).

#define NROWS   1024
#define ROWLEN  9216
#define NV4     2304
#define NT      256
#define NGROUP  4
#define NWARP   8

// shared layout (dynamic):
//   [0,     36864) s_w    : row of 9216 floats
//   [36864, 46080) s_r    : 9216 int8 rounded values
//   [46080, 46144) s_red  : 16 floats (per-warp max[8], min[8])
//   [46144, 46176) s_sum  : 8 floats  (per-warp residual-error sums)
//   [46176, 46240) s_cnt  : 2 x 8 ints (parity double-buffered counts)
#define SMEM_BYTES 46240

__device__ __forceinline__ float warpSum(float v) {
#pragma unroll
    for (int o = 16; o; o >>= 1) v += __shfl_xor_sync(0xffffffffu, v, o);
    return v;
}
__device__ __forceinline__ float warpMaxR(float v) {
#pragma unroll
    for (int o = 16; o; o >>= 1) v = fmaxf(v, __shfl_xor_sync(0xffffffffu, v, o));
    return v;
}
__device__ __forceinline__ float warpMinR(float v) {
#pragma unroll
    for (int o = 16; o; o >>= 1) v = fminf(v, __shfl_xor_sync(0xffffffffu, v, o));
    return v;
}

// block-wide count of c_local (0..4 per thread) in ONE barrier.
__device__ __forceinline__ int blockCount(int c_local, int* s_cnt, int parity,
                                          int wid, int lane) {
    int cw = __reduce_add_sync(0xffffffffu, c_local);
    if (lane == 0) s_cnt[parity * NWARP + wid] = cw;
    __syncthreads();
    int t = 0;
#pragma unroll
    for (int i = 0; i < NWARP; i++) t += s_cnt[parity * NWARP + i];
    return t;
}

__global__ void __launch_bounds__(NT, 4)
squant_kernel(const float* __restrict__ w, float* __restrict__ out)
{
    extern __shared__ unsigned char smem[];
    float*       s_w   = (float*)smem;
    signed char* s_r   = (signed char*)(smem + 36864);
    float*       s_red = (float*)(smem + 46080);
    float*       s_sum = (float*)(smem + 46144);
    int*         s_cnt = (int*)(smem + 46176);

    const int tid  = threadIdx.x;
    const int lane = tid & 31;
    const int wid  = tid >> 5;

    const float4* __restrict__ w4 = (const float4*)(w + (size_t)blockIdx.x * ROWLEN);
    float4* sw4 = (float4*)s_w;

    // ---- vectorized load + min/max (1 barrier) ----
    float vmax = -FLT_MAX, vmin = FLT_MAX;
#pragma unroll
    for (int i = tid; i < NV4; i += NT) {
        float4 v = w4[i];
        sw4[i] = v;
        vmax = fmaxf(vmax, fmaxf(fmaxf(v.x, v.y), fmaxf(v.z, v.w)));
        vmin = fminf(vmin, fminf(fminf(v.x, v.y), fminf(v.z, v.w)));
    }
    vmax = warpMaxR(vmax);
    vmin = warpMinR(vmin);
    if (lane == 0) { s_red[wid] = vmax; s_red[NWARP + wid] = vmin; }
    __syncthreads();                       // also publishes s_w
    float m = s_red[0], n = s_red[NWARP];
#pragma unroll
    for (int i = 1; i < NWARP; i++) {
        m = fmaxf(m, s_red[i]);
        n = fminf(n, s_red[NWARP + i]);
    }
    const float scale = 15.0f / fmaxf(m - n, 1e-8f);
    const float zp    = rintf(scale * n) + 8.0f;

    // ---- pass 1: SQuant-K, 4 groups/thread, float-domain selection ----
    float    Pup[NGROUP], Pdn[NGROUP];
    unsigned IVup[NGROUP], IVdn[NGROUP];   // (elem_idx << 8) | (val + 32)
    float er_tot = 0.f;

#pragma unroll
    for (int g = 0; g < NGROUP; g++) {
        const int base = (g * NT + tid) * 9;
        float rv[9], ev[9], pup[9], pdn[9];
        float e = 0.f;
#pragma unroll
        for (int j = 0; j < 9; j++) {
            float qq = fmaf(scale, s_w[base + j], -zp);
            float rr = rintf(qq);
            float ee = rr - qq;
            rv[j] = rr; ev[j] = ee;
            // candidate priorities as floats (0 = non-candidate)
            pup[j] = (ee < 0.f && qq <  7.f) ? -ee : 0.f;
            pdn[j] = (ee > 0.f && qq > -8.f) ?  ee : 0.f;
            e += ee;
        }
        const bool  is_up = (e < 0.f);
        const float dir   = is_up ? 1.f : -1.f;
        float nf = rintf(fabsf(e));          // mathematically <= 5
        nf = fminf(nf, 8.f);

        float pf[9];
#pragma unroll
        for (int j = 0; j < 9; j++) pf[j] = is_up ? pup[j] : pdn[j];

        // stable descending ranks, float accumulators (fma pipe)
        float rk[9];
#pragma unroll
        for (int j = 0; j < 9; j++) rk[j] = 0.f;
#pragma unroll
        for (int j = 1; j < 9; j++)
#pragma unroll
            for (int i = 0; i < j; i++) {
                bool c = pf[i] >= pf[j];     // identical to uint-bit compare (nonneg)
                rk[j] += c ? 1.f : 0.f;
                rk[i] += c ? 0.f : 1.f;
            }

        const float nfm1 = nf - 1.f;
        float er = 0.f;
        float pN = 0.f, pL = 0.f, vN = 0.f, vL = 0.f;
        int iN = 0, iL = 0;
#pragma unroll
        for (int j = 0; j < 9; j++) {
            bool  cnd   = pf[j] > 0.f;               // candidate in chosen direction
            float delta = cnd ? dir : 0.f;
            bool  f     = rk[j] < nf;
            float nr = f ? (rv[j] + delta) : rv[j];
            float ne = f ? (cnd ? (ev[j] + delta) : 0.f) : ev[j];
            er += ne;
            s_r[base + j] = (signed char)__float2int_rn(nr);
            if (rk[j] == nf)   { pN = pf[j]; vN = rv[j] + delta; iN = j; }
            if (rk[j] == nfm1) { pL = pf[j]; vL = rv[j];         iL = j; }
        }
        er_tot += er;

        const bool  hasL = (nf > 0.f);
        const float priN = pN;                           // cand ? |err| : 0
        const float priL = hasL ? (1.f - pL) : 0.f;      // revert-last priority
        const float valL = hasL ? vL : vN;
        const int   idxN = base + iN;
        const int   idxL = hasL ? (base + iL) : idxN;
        const unsigned ivN = ((unsigned)idxN << 8) | (unsigned)(__float2int_rn(vN)   + 32);
        const unsigned ivL = ((unsigned)idxL << 8) | (unsigned)(__float2int_rn(valL) + 32);

        if (is_up) { Pup[g] = priN; IVup[g] = ivN; Pdn[g] = priL; IVdn[g] = ivL; }
        else       { Pdn[g] = priN; IVdn[g] = ivN; Pup[g] = priL; IVup[g] = ivL; }
    }

    // ---- row residual-error reduction (1 barrier) ----
    {
        float s = warpSum(er_tot);
        if (lane == 0) s_sum[wid] = s;
    }
    __syncthreads();
    float e2 = s_sum[0];
#pragma unroll
    for (int i = 1; i < NWARP; i++) e2 += s_sum[i];

    const bool up2 = (e2 < 0.f);
    int k = (int)rintf(fabsf(e2));
    if (k > NT * NGROUP) k = NT * NGROUP;

    unsigned U[NGROUP], IV[NGROUP];
#pragma unroll
    for (int g = 0; g < NGROUP; g++) {
        U[g]  = __float_as_uint(up2 ? Pup[g] : Pdn[g]);   // P >= 0 -> bits monotone
        IV[g] = up2 ? IVup[g] : IVdn[g];
    }

    // ---- pass-2 selection: value-guided bisection for k-th largest ----
    if (k > 0) {
        int parity = 0;
        unsigned lo = 0u, hi = 0x3F800000u;   // invariant: cnt(>=lo)>=k, cnt(>=hi+1)<k
        bool found = false;
        unsigned thr = 0;
        while (lo < hi) {
            float midf = 0.5f * (__uint_as_float(lo) + __uint_as_float(hi));
            unsigned mid = __float_as_uint(midf);
            if (mid <= lo) mid = lo + 1;
            else if (mid > hi) mid = hi;
            int cl = (U[0] >= mid) + (U[1] >= mid) + (U[2] >= mid) + (U[3] >= mid);
            int c = blockCount(cl, s_cnt, parity, wid, lane); parity ^= 1;
            if (c == k) { thr = mid; found = true; break; }
            if (c > k) lo = mid; else hi = mid - 1;
        }
        if (found) {
#pragma unroll
            for (int g = 0; g < NGROUP; g++)
                if (U[g] >= thr)
                    s_r[IV[g] >> 8] = (signed char)((int)(IV[g] & 0xFFu) - 32);
        } else {
            // exact ties at the k-th priority: resolve by ascending element index
            const unsigned Uk = lo;
            int clg = (U[0] > Uk) + (U[1] > Uk) + (U[2] > Uk) + (U[3] > Uk);
            int cGT = blockCount(clg, s_cnt, parity, wid, lane); parity ^= 1;
            int rem = k - cGT;                  // >= 1
            int ilo = 0, ihi = ROWLEN, mI = ROWLEN;
            for (;;) {
                mI = (ilo + ihi + 1) >> 1;
                int ct = ((U[0] == Uk) && (int)(IV[0] >> 8) < mI)
                       + ((U[1] == Uk) && (int)(IV[1] >> 8) < mI)
                       + ((U[2] == Uk) && (int)(IV[2] >> 8) < mI)
                       + ((U[3] == Uk) && (int)(IV[3] >> 8) < mI);
                int c = blockCount(ct, s_cnt, parity, wid, lane); parity ^= 1;
                if (c == rem) break;            // unique indices -> always reachable
                if (c < rem) ilo = mI; else ihi = mI - 1;
            }
#pragma unroll
            for (int g = 0; g < NGROUP; g++)
                if (U[g] > Uk || (U[g] == Uk && (int)(IV[g] >> 8) < mI))
                    s_r[IV[g] >> 8] = (signed char)((int)(IV[g] & 0xFFu) - 32);
        }
    }
    __syncthreads();

    // ---- clip + dequantize (packed clip, reciprocal multiply) ----
    const float inv   = 1.0f / scale;
    const float zpinv = zp * inv;
    float4* __restrict__ orow4 = (float4*)(out + (size_t)blockIdx.x * ROWLEN);
    const int* s_ri = (const int*)s_r;
#pragma unroll
    for (int i = tid; i < NV4; i += NT) {
        int p = s_ri[i];
        p = __vmins4(__vmaxs4(p, 0xF8F8F8F8), 0x07070707);   // clip bytes to [-8,7]
        float4 o;
        o.x = fmaf((float)(int)(signed char)(p),       inv, zpinv);
        o.y = fmaf((float)(int)(signed char)(p >> 8),  inv, zpinv);
        o.z = fmaf((float)(int)(signed char)(p >> 16), inv, zpinv);
        o.w = fmaf((float)(int)(signed char)(p >> 24), inv, zpinv);
        orow4[i] = o;
    }
}

extern "C" void kernel_launch(void* const* d_in, const int* in_sizes, int n_in,
                              void* d_out, int out_size)
{
    const float* w = (const float*)d_in[0];
    float* out = (float*)d_out;
    squant_kernel<<<NROWS, NT, SMEM_BYTES>>>(w, out);
}